// round 16
// baseline (speedup 1.0000x reference)
#include <cuda_runtime.h>
#include <cuda_fp16.h>
#include <cstdint>
#include <cstddef>

#define D 128
#define HID 384
#define MAXN 100000
#define MAXE 500000
#define MAXG 5000

// ---------------------------------------------------------------------------
// Scratch layout (floats)
// ---------------------------------------------------------------------------
static const size_t OFF_ZB = 0;                                    // E*384 fp32
static const size_t OFF_PH = OFF_ZB + (size_t)MAXE * HID;          // N*384 halves
static const size_t OFF_U1 = OFF_PH + (size_t)MAXN * HID;          // G*384 fp32
static const size_t OFF_ZA = OFF_U1 + (size_t)MAXG * HID;          // N*384 fp32
static const size_t OFF_ZG = OFF_ZA + (size_t)MAXN * HID;          // G*384 fp32
static const size_t OFF_SH = OFF_ZG + (size_t)MAXG * HID;          // N*128
static const size_t OFF_SE = OFF_SH + (size_t)MAXN * D;            // N*128
static const size_t OFF_UH = OFF_SE + (size_t)MAXN * D;            // G*128
static const size_t OFF_UE = OFF_UH + (size_t)MAXG * D;            // G*128
static const size_t OFF_ST = OFF_UE + (size_t)MAXG * D;            // 4*384
static const size_t OFF_WP   = OFF_ST + 4 * HID;                   // 589824 halves
static const size_t OFF_XA16 = OFF_WP + 294912;                    // N*384 halves
static const size_t OFF_XG16 = OFF_XA16 + (size_t)MAXN * HID / 2;  // G*384 halves
static const size_t OFF_E16  = OFF_XG16 + (size_t)MAXG * HID / 2;  // E*128 halves
static const size_t OFF_H16  = OFF_E16 + (size_t)MAXE * D / 2;     // N*128 halves
static const size_t OFF_U16  = OFF_H16 + (size_t)MAXN * D / 2;     // G*128 halves
static const size_t TOTAL_SCRATCH = OFF_U16 + (size_t)MAXG * D / 2 + 1024;

__device__ __align__(256) float g_scratch[TOTAL_SCRATCH];

// Prepped-weight offsets in half elements (dense fp16).
#define WPO_BW1A 0
#define WPO_BW1B 49152
#define WPO_BW1C 98304
#define WPO_BW2  147456
#define WPO_AW1  196608
#define WPO_AW2  344064
#define WPO_GW1  393216
#define WPO_GW2  540672

// ---------------------------------------------------------------------------
// PTX helpers
// ---------------------------------------------------------------------------
__device__ __forceinline__ uint32_t smem_u32(const void* p) {
    uint32_t a;
    asm("{ .reg .u64 t; cvta.to.shared.u64 t, %1; cvt.u32.u64 %0, t; }" : "=r"(a) : "l"(p));
    return a;
}
__device__ __forceinline__ void ldsm4(uint32_t (&r)[4], uint32_t addr) {
    asm volatile("ldmatrix.sync.aligned.m8n8.x4.shared.b16 {%0,%1,%2,%3}, [%4];"
                 : "=r"(r[0]), "=r"(r[1]), "=r"(r[2]), "=r"(r[3]) : "r"(addr));
}
__device__ __forceinline__ void ldsm4t(uint32_t (&r)[4], uint32_t addr) {
    asm volatile("ldmatrix.sync.aligned.m8n8.x4.trans.shared.b16 {%0,%1,%2,%3}, [%4];"
                 : "=r"(r[0]), "=r"(r[1]), "=r"(r[2]), "=r"(r[3]) : "r"(addr));
}
__device__ __forceinline__ void mma16816(float (&c)[4], const uint32_t (&a)[4],
                                         uint32_t b0, uint32_t b1) {
    asm volatile(
        "mma.sync.aligned.m16n8k16.row.col.f32.f16.f16.f32 "
        "{%0,%1,%2,%3}, {%4,%5,%6,%7}, {%8,%9}, {%0,%1,%2,%3};"
        : "+f"(c[0]), "+f"(c[1]), "+f"(c[2]), "+f"(c[3])
        : "r"(a[0]), "r"(a[1]), "r"(a[2]), "r"(a[3]), "r"(b0), "r"(b1));
}
__device__ __forceinline__ uint32_t packh2(float x, float y) {
    __half2 p = __halves2half2(__float2half_rn(x), __float2half_rn(y));
    return *(uint32_t*)&p;
}
__device__ __forceinline__ void cp_async16(uint32_t saddr, const void* gaddr) {
    asm volatile("cp.async.cg.shared.global [%0], [%1], 16;" :: "r"(saddr), "l"(gaddr));
}
__device__ __forceinline__ void cp_async16z(uint32_t saddr, const void* gaddr, bool valid) {
    int sz = valid ? 16 : 0;
    asm volatile("cp.async.cg.shared.global [%0], [%1], 16, %2;"
                 :: "r"(saddr), "l"(gaddr), "r"(sz));
}
__device__ __forceinline__ void cp_commit() {
    asm volatile("cp.async.commit_group;" ::: "memory");
}
__device__ __forceinline__ void cp_wait2() {
    asm volatile("cp.async.wait_group 2;" ::: "memory");
}

// ---------------------------------------------------------------------------
// Fused prep kernels
// ---------------------------------------------------------------------------
__global__ void cvt_all(const float* __restrict__ e, const float* __restrict__ h,
                        const float* __restrict__ u,
                        __half* __restrict__ e16, __half* __restrict__ h16,
                        __half* __restrict__ u16, int ne4, int nh4, int nu4)
{
    int i = blockIdx.x * blockDim.x + threadIdx.x;
    const float* src; __half* dst; int j;
    if (i < ne4) { src = e; dst = e16; j = i; }
    else if (i < ne4 + nh4) { src = h; dst = h16; j = i - ne4; }
    else if (i < ne4 + nh4 + nu4) { src = u; dst = u16; j = i - ne4 - nh4; }
    else return;
    float4 v = ((const float4*)src)[j];
    uint2 w;
    w.x = packh2(v.x, v.y);
    w.y = packh2(v.z, v.w);
    ((uint2*)dst)[j] = w;
}

#define T1 49152
#define T2 147456
#define T3 49152
__global__ void prep_all(const float* __restrict__ bW1, const float* __restrict__ bW2,
                         const float* __restrict__ aW1, const float* __restrict__ aW2,
                         const float* __restrict__ gW1, const float* __restrict__ gW2,
                         __half* __restrict__ WP)
{
    int i = blockIdx.x * blockDim.x + threadIdx.x;
    const float* src; int dstoff;
    if      (i < T1)                  { src = bW1;               dstoff = WPO_BW1A; }
    else if (i < 2*T1)                { src = bW1 + T1;          dstoff = WPO_BW1B; i -= T1; }
    else if (i < 3*T1)                { src = bW1 + 2*T1;        dstoff = WPO_BW1C; i -= 2*T1; }
    else if (i < 3*T1 + T3)           { src = bW2;               dstoff = WPO_BW2;  i -= 3*T1; }
    else if (i < 3*T1 + T3 + T2)      { src = aW1;               dstoff = WPO_AW1;  i -= 3*T1 + T3; }
    else if (i < 3*T1 + 2*T3 + T2)    { src = aW2;               dstoff = WPO_AW2;  i -= 3*T1 + T3 + T2; }
    else if (i < 3*T1 + 2*T3 + 2*T2)  { src = gW1;               dstoff = WPO_GW1;  i -= 3*T1 + 2*T3 + T2; }
    else if (i < 3*T1 + 3*T3 + 2*T2)  { src = gW2;               dstoff = WPO_GW2;  i -= 3*T1 + 2*T3 + 2*T2; }
    else return;
    WP[dstoff + i] = __float2half_rn(src[i]);
}

// ---------------------------------------------------------------------------
// mma.sync GEMM, 64x128 CTA tile (R16: occupancy 2 -> 3 CTAs/SM).
// 8 warps as 4x2, warp tile 16x64 (acc 32 regs). KC=32, 4-stage cp.async ring.
//  HALFA: A fp16 in gmem, staged via cp.async (4-stage)
//  BNA:   (fp32 A) relu(a*scale+shift) at staging (A: reg prefetch + 2-stage)
//  GATH / SCAT / STATS / HSCAT / HALFC: as before
// ---------------------------------------------------------------------------
#define APAD 80
#define BPAD 272
#define ASTAGE 5120          // 64 rows * 80 B
#define BSTAGE 8704
#define SM_B    20480        // 4 * ASTAGE
#define SM_SSC  55296        // SM_B + 4 * BSTAGE
#define SM_SSH  56832
#define SM_SSUM 58368
#define SM_SSQ  58880
#define SMEM_BYTES 59392

template<bool HALFA, bool BNA, bool SCAT, bool GATH, bool STATS, bool HSCAT, bool HALFC>
__global__ void __launch_bounds__(256, 3)
gemm_mma(const void* __restrict__ Avoid, const __half* __restrict__ Bp,
         const float* __restrict__ bias, void* __restrict__ Cvoid,
         int M, int K, int Nd,
         const float* __restrict__ bnscale, const float* __restrict__ bnshift,
         const int* __restrict__ seg, float* __restrict__ segout,
         const __half* __restrict__ Ph16, const float* __restrict__ U1,
         const int* __restrict__ src, const int* __restrict__ dst,
         const int* __restrict__ gid,
         float* __restrict__ st_sum, float* __restrict__ st_sq,
         const float* __restrict__ Hg, float* __restrict__ SHg)
{
    extern __shared__ __align__(16) char smem[];
    float* ssc  = (float*)(smem + SM_SSC);
    float* ssh  = (float*)(smem + SM_SSH);
    float* ssum = (float*)(smem + SM_SSUM);
    float* ssq  = (float*)(smem + SM_SSQ);

    const int tid  = threadIdx.x;
    const int wid  = tid >> 5;
    const int lane = tid & 31;
    const int wm   = wid & 3;     // warp row (16 rows)
    const int wn   = wid >> 2;    // warp col (64 cols)
    const int row0 = blockIdx.y * 64;
    const int col0 = blockIdx.x * 128;

    if (BNA) {
        for (int i = tid; i < K; i += 256) { ssc[i] = bnscale[i]; ssh[i] = bnshift[i]; }
    }
    if (STATS && tid < 128) { ssum[tid] = 0.f; ssq[tid] = 0.f; }

    // ---- staging thread mapping: 64 rows x 32 halves per stage = 16B/thread ----
    const int arow = tid >> 2;            // 0..63
    const int acol = (tid & 3) * 8;       // element offset, 8 elems (16B fp16 / 32B fp32)
    const bool avalid = (row0 + arow) < M;
    const float*  Af = (const float*) Avoid + (size_t)(row0 + arow) * K + acol;
    const __half* Ah = (const __half*)Avoid + (size_t)(row0 + arow) * K + acol;

    const int brow = tid >> 3;
    const int bcol = (tid & 7) * 16;

    float acc[8][4];
    #pragma unroll
    for (int j = 0; j < 8; j++)
        #pragma unroll
        for (int q = 0; q < 4; q++) acc[j][q] = 0.f;

    const uint32_t sbase = smem_u32(smem);
    const uint32_t aoff = (uint32_t)((lane & 15) * APAD + (lane >> 4) * 16);
    const uint32_t boff = (uint32_t)((((lane >> 3) & 1) * 8 + (lane & 7)) * BPAD + (lane >> 4) * 16);

    const int nchunk = K >> 5;           // >= 4 (K in {128, 384})
    const uint32_t bdst = (uint32_t)(brow * BPAD + bcol * 2);
    const uint32_t adst = (uint32_t)(arow * APAD + acol * 2);

    float4 aval[2];   // fp32-path register prefetch (8 floats)

    // ---- prologue: issue stages 0,1,2 ----
    #pragma unroll
    for (int s = 0; s < 3; s++) {
        const uint32_t bs = sbase + SM_B + (uint32_t)(s * BSTAGE);
        const __half* bp = Bp + (size_t)(s * 32 + brow) * Nd + col0 + bcol;
        cp_async16(bs + bdst, bp);
        cp_async16(bs + bdst + 16, bp + 8);
        if (HALFA) {
            const uint32_t as = sbase + (uint32_t)(s * ASTAGE);
            cp_async16z(as + adst, Ah + s * 32, avalid);
        }
        cp_commit();
    }
    if (!HALFA) {
        if (avalid) {
            aval[0] = *(const float4*)(Af);
            aval[1] = *(const float4*)(Af + 4);
        } else {
            aval[0] = make_float4(0.f, 0.f, 0.f, 0.f);
            aval[1] = make_float4(0.f, 0.f, 0.f, 0.f);
        }
    }
    __syncthreads();   // publish ssc/ssh/ssum before iter-0 BNA store reads them

    for (int c = 0; c < nchunk; c++) {
        // fp32 path: convert+store A chunk c into its 2-stage buffer.
        if (!HALFA) {
            char* ah = smem + (c & 1) * ASTAGE + adst;
            #pragma unroll
            for (int q = 0; q < 2; q++) {
                float4 v = aval[q];
                if (BNA) {
                    const int k = c * 32 + acol + q * 4;
                    v.x = fmaxf(fmaf(v.x, ssc[k + 0], ssh[k + 0]), 0.f);
                    v.y = fmaxf(fmaf(v.y, ssc[k + 1], ssh[k + 1]), 0.f);
                    v.z = fmaxf(fmaf(v.z, ssc[k + 2], ssh[k + 2]), 0.f);
                    v.w = fmaxf(fmaf(v.w, ssc[k + 3], ssh[k + 3]), 0.f);
                }
                uint2 hv;
                hv.x = packh2(v.x, v.y);
                hv.y = packh2(v.z, v.w);
                *(uint2*)(ah + q * 8) = hv;
            }
        }
        cp_wait2();
        __syncthreads();   // publishes stage c (+ fp32-A stores)
        // Issue stage c+3 into ring slot (c+3)&3; reads of that slot finished
        // in compute(c-1), ordered before this point by this sync.
        {
            const int s = c + 3;
            if (s < nchunk) {
                const uint32_t bs = sbase + SM_B + (uint32_t)((s & 3) * BSTAGE);
                const __half* bp = Bp + (size_t)(s * 32 + brow) * Nd + col0 + bcol;
                cp_async16(bs + bdst, bp);
                cp_async16(bs + bdst + 16, bp + 8);
                if (HALFA) {
                    const uint32_t as = sbase + (uint32_t)((s & 3) * ASTAGE);
                    cp_async16z(as + adst, Ah + s * 32, avalid);
                }
            }
            cp_commit();
        }
        if (!HALFA && c + 1 < nchunk && avalid) {
            const float* ap = Af + (c + 1) * 32;
            aval[0] = *(const float4*)(ap);
            aval[1] = *(const float4*)(ap + 4);
        }
        // ---- compute chunk c ----
        const uint32_t aBc = sbase + (uint32_t)((HALFA ? (c & 3) : (c & 1)) * ASTAGE);
        const uint32_t bBc = sbase + SM_B + (uint32_t)((c & 3) * BSTAGE);
        #pragma unroll
        for (int kk = 0; kk < 2; kk++) {
            uint32_t af[4], bx[8][2];
            #pragma unroll
            for (int p = 0; p < 4; p++) {
                uint32_t r[4];
                ldsm4t(r, bBc + boff + (uint32_t)(kk * 16 * BPAD + (64 * wn + p * 16) * 2));
                bx[2 * p][0] = r[0]; bx[2 * p][1] = r[1];
                bx[2 * p + 1][0] = r[2]; bx[2 * p + 1][1] = r[3];
            }
            ldsm4(af, aBc + aoff + (uint32_t)(16 * wm * APAD + kk * 32));
            #pragma unroll
            for (int j = 0; j < 8; j++)
                mma16816(acc[j], af, bx[j][0], bx[j][1]);
        }
    }

    // ---- epilogue ----
    const int m4 = lane >> 2;
    const int n2 = (lane & 3) * 2;
    const bool do_hscat = HSCAT && (col0 == 0);

    float bcolv[16];
    #pragma unroll
    for (int j = 0; j < 8; j++) {
        if (bias) {
            float2 b2 = *(const float2*)(bias + col0 + 64 * wn + 8 * j + n2);
            bcolv[2 * j] = b2.x; bcolv[2 * j + 1] = b2.y;
        } else {
            bcolv[2 * j] = 0.f; bcolv[2 * j + 1] = 0.f;
        }
    }
    float csum[16], csq[16];
    if (STATS) {
        #pragma unroll
        for (int q = 0; q < 16; q++) { csum[q] = 0.f; csq[q] = 0.f; }
    }

    const int rb = row0 + 16 * wm + m4;
    #pragma unroll
    for (int hf = 0; hf < 2; hf++) {
        const int r = rb + 8 * hf;
        if (r >= M) continue;
        int si = 0, di = 0, gi2 = 0, sg = 0;
        if (GATH) { si = src[r]; di = dst[r]; gi2 = gid[si]; }
        if (SCAT) sg = seg[r];
        #pragma unroll
        for (int j = 0; j < 8; j++) {
            const int gc = col0 + 64 * wn + 8 * j + n2;
            float v0 = acc[j][2 * hf]     + bcolv[2 * j];
            float v1 = acc[j][2 * hf + 1] + bcolv[2 * j + 1];
            if (GATH) {
                __half2 p1 = *(const __half2*)(Ph16 + (size_t)si * HID + gc);
                __half2 p2 = *(const __half2*)(Ph16 + (size_t)di * HID + gc);
                float2 f1 = __half22float2(p1);
                float2 f2 = __half22float2(p2);
                float2 g3 = *(const float2*)(U1 + (size_t)gi2 * HID + gc);
                v0 += f1.x + f2.x + g3.x;
                v1 += f1.y + f2.y + g3.y;
            }
            if (HALFC) {
                *(uint32_t*)((__half*)Cvoid + (size_t)r * Nd + gc) = packh2(v0, v1);
            } else {
                *(float2*)((float*)Cvoid + (size_t)r * Nd + gc) = make_float2(v0, v1);
            }
            if (SCAT) {
                float* so = segout + (size_t)sg * Nd + gc;
                atomicAdd(so, v0); atomicAdd(so + 1, v1);
            }
            if (do_hscat) {
                float2 hv2 = *(const float2*)(Hg + (size_t)si * D + gc);
                float* so2 = SHg + (size_t)di * D + gc;
                atomicAdd(so2, hv2.x); atomicAdd(so2 + 1, hv2.y);
            }
            if (STATS) {
                csum[2 * j] += v0;     csq[2 * j] += v0 * v0;
                csum[2 * j + 1] += v1; csq[2 * j + 1] += v1 * v1;
            }
        }
    }
    if (STATS) {
        #pragma unroll
        for (int j = 0; j < 8; j++) {
            const int cl0 = 64 * wn + 8 * j + n2;
            atomicAdd(&ssum[cl0], csum[2 * j]);
            atomicAdd(&ssum[cl0 + 1], csum[2 * j + 1]);
            atomicAdd(&ssq[cl0], csq[2 * j]);
            atomicAdd(&ssq[cl0 + 1], csq[2 * j + 1]);
        }
        __syncthreads();
        if (tid < 128) {
            atomicAdd(&st_sum[col0 + tid], ssum[tid]);
            atomicAdd(&st_sq[col0 + tid], ssq[tid]);
        }
    }
}

// ---------------------------------------------------------------------------
// Elementwise kernels
// ---------------------------------------------------------------------------
__global__ void zerok(float* __restrict__ p, size_t n) {
    size_t i = (size_t)blockIdx.x * blockDim.x + threadIdx.x;
    size_t st = (size_t)gridDim.x * blockDim.x;
    for (; i < n; i += st) p[i] = 0.f;
}

__global__ void bn_prep(float* __restrict__ sum, float* __restrict__ sq,
                        const float* __restrict__ g1, const float* __restrict__ beta1,
                        float* __restrict__ scale, float* __restrict__ shift, float invM)
{
    const int c = threadIdx.x;
    float mean = sum[c] * invM;
    float var  = sq[c] * invM - mean * mean;
    float rstd = rsqrtf(var + 1e-5f);
    float sc = rstd * g1[c];
    scale[c] = sc;
    shift[c] = beta1[c] - mean * sc;
    sum[c] = 0.f;
    sq[c] = 0.f;
}

__global__ void node_build(const float* __restrict__ h, const float* __restrict__ u,
                           const int* __restrict__ gid,
                           const float* __restrict__ SH, const float* __restrict__ SE,
                           __half* __restrict__ Xa16, float* __restrict__ UE, int N)
{
    int idx = blockIdx.x * blockDim.x + threadIdx.x;
    int tot = N * 32;
    if (idx >= tot) return;
    int n = idx >> 5;
    int c = (idx & 31) << 2;
    int g = gid[n];
    float4 sh = *(const float4*)&SH[(size_t)n * D + c];
    float4 hv = *(const float4*)&h[(size_t)n * D + c];
    float4 se = *(const float4*)&SE[(size_t)n * D + c];
    float4 uv = *(const float4*)&u[(size_t)g * D + c];
    size_t base = (size_t)n * HID;
    uint2 w;
    w.x = packh2(sh.x + hv.x, sh.y + hv.y);
    w.y = packh2(sh.z + hv.z, sh.w + hv.w);
    *(uint2*)&Xa16[base + c] = w;
    w.x = packh2(se.x, se.y);
    w.y = packh2(se.z, se.w);
    *(uint2*)&Xa16[base + D + c] = w;
    w.x = packh2(uv.x, uv.y);
    w.y = packh2(uv.z, uv.w);
    *(uint2*)&Xa16[base + 2 * D + c] = w;
    float* o = UE + (size_t)g * D + c;
    atomicAdd(o + 0, 0.5f * se.x); atomicAdd(o + 1, 0.5f * se.y);
    atomicAdd(o + 2, 0.5f * se.z); atomicAdd(o + 3, 0.5f * se.w);
}

__global__ void graph_build(const float* __restrict__ u, const float* __restrict__ UH,
                            const float* __restrict__ UE, __half* __restrict__ Xg16, int G)
{
    int idx = blockIdx.x * blockDim.x + threadIdx.x;
    int tot = G * 32;
    if (idx >= tot) return;
    int g = idx >> 5;
    int c = (idx & 31) << 2;
    size_t base = (size_t)g * HID;
    float4 a = *(const float4*)&UH[(size_t)g * D + c];
    float4 b = *(const float4*)&UE[(size_t)g * D + c];
    float4 d = *(const float4*)&u[(size_t)g * D + c];
    uint2 w;
    w.x = packh2(a.x, a.y); w.y = packh2(a.z, a.w);
    *(uint2*)&Xg16[base + c] = w;
    w.x = packh2(b.x, b.y); w.y = packh2(b.z, b.w);
    *(uint2*)&Xg16[base + D + c] = w;
    w.x = packh2(d.x, d.y); w.y = packh2(d.z, d.w);
    *(uint2*)&Xg16[base + 2 * D + c] = w;
}

// ---------------------------------------------------------------------------
// Dispatch.
// mode 0: HALFA plain            mode 5: HALFA + HALFC (Ph output fp16)
// mode 1: HALFA GATH+STATS+HSCAT mode 2: fp32 BNA+SCAT
// mode 3: HALFA STATS            mode 4: fp32 BNA
// ---------------------------------------------------------------------------
static void run_gemm_mma(int mode,
                         const void* A, const __half* Bp, const float* bias, void* C,
                         int M, int K, int Nd,
                         const float* sc, const float* sh,
                         const int* seg, float* segout,
                         const __half* Ph16, const float* U1,
                         const int* src, const int* dst, const int* gid,
                         float* st_sum, float* st_sq,
                         const float* Hg, float* SHg)
{
    dim3 grid(Nd / 128, (M + 63) / 64);
    switch (mode) {
    case 0:
        cudaFuncSetAttribute(gemm_mma<true ,false,false,false,false,false,false>, cudaFuncAttributeMaxDynamicSharedMemorySize, SMEM_BYTES);
        gemm_mma<true ,false,false,false,false,false,false><<<grid,256,SMEM_BYTES>>>(A,Bp,bias,C,M,K,Nd,sc,sh,seg,segout,Ph16,U1,src,dst,gid,st_sum,st_sq,Hg,SHg);
        break;
    case 5:
        cudaFuncSetAttribute(gemm_mma<true ,false,false,false,false,false,true >, cudaFuncAttributeMaxDynamicSharedMemorySize, SMEM_BYTES);
        gemm_mma<true ,false,false,false,false,false,true ><<<grid,256,SMEM_BYTES>>>(A,Bp,bias,C,M,K,Nd,sc,sh,seg,segout,Ph16,U1,src,dst,gid,st_sum,st_sq,Hg,SHg);
        break;
    case 1:
        cudaFuncSetAttribute(gemm_mma<true ,false,false,true ,true ,true ,false>, cudaFuncAttributeMaxDynamicSharedMemorySize, SMEM_BYTES);
        gemm_mma<true ,false,false,true ,true ,true ,false><<<grid,256,SMEM_BYTES>>>(A,Bp,bias,C,M,K,Nd,sc,sh,seg,segout,Ph16,U1,src,dst,gid,st_sum,st_sq,Hg,SHg);
        break;
    case 2:
        cudaFuncSetAttribute(gemm_mma<false,true ,true ,false,false,false,false>, cudaFuncAttributeMaxDynamicSharedMemorySize, SMEM_BYTES);
        gemm_mma<false,true ,true ,false,false,false,false><<<grid,256,SMEM_BYTES>>>(A,Bp,bias,C,M,K,Nd,sc,sh,seg,segout,Ph16,U1,src,dst,gid,st_sum,st_sq,Hg,SHg);
        break;
    case 3:
        cudaFuncSetAttribute(gemm_mma<true ,false,false,false,true ,false,false>, cudaFuncAttributeMaxDynamicSharedMemorySize, SMEM_BYTES);
        gemm_mma<true ,false,false,false,true ,false,false><<<grid,256,SMEM_BYTES>>>(A,Bp,bias,C,M,K,Nd,sc,sh,seg,segout,Ph16,U1,src,dst,gid,st_sum,st_sq,Hg,SHg);
        break;
    case 4:
        cudaFuncSetAttribute(gemm_mma<false,true ,false,false,false,false,false>, cudaFuncAttributeMaxDynamicSharedMemorySize, SMEM_BYTES);
        gemm_mma<false,true ,false,false,false,false,false><<<grid,256,SMEM_BYTES>>>(A,Bp,bias,C,M,K,Nd,sc,sh,seg,segout,Ph16,U1,src,dst,gid,st_sum,st_sq,Hg,SHg);
        break;
    }
}

extern "C" void kernel_launch(void* const* d_in, const int* in_sizes, int n_in,
                              void* d_out, int out_size)
{
    const float* h   = (const float*)d_in[0];
    const float* e   = (const float*)d_in[1];
    const float* u   = (const float*)d_in[2];
    const int*   src = (const int*)d_in[3];
    const int*   dst = (const int*)d_in[4];
    const int*   gid = (const int*)d_in[5];

    const float* bW1 = (const float*)d_in[6];
    const float* bb1 = (const float*)d_in[7];
    const float* bg1 = (const float*)d_in[8];
    const float* bbt = (const float*)d_in[9];
    const float* bW2 = (const float*)d_in[10];
    const float* bb2 = (const float*)d_in[11];

    const float* aW1 = (const float*)d_in[12];
    const float* ab1 = (const float*)d_in[13];
    const float* ag1 = (const float*)d_in[14];
    const float* abt = (const float*)d_in[15];
    const float* aW2 = (const float*)d_in[16];
    const float* ab2 = (const float*)d_in[17];

    const float* gW1 = (const float*)d_in[18];
    const float* gb1 = (const float*)d_in[19];
    const float* gg1 = (const float*)d_in[20];
    const float* gbt = (const float*)d_in[21];
    const float* gW2 = (const float*)d_in[22];
    const float* gb2 = (const float*)d_in[23];

    const int N = in_sizes[5];
    const int E = in_sizes[3];
    const int G = in_sizes[2] / D;

    float* scratch = nullptr;
    cudaGetSymbolAddress((void**)&scratch, g_scratch);

    float* Zb = scratch + OFF_ZB;
    __half* Ph16 = (__half*)(scratch + OFF_PH);
    float* U1 = scratch + OFF_U1;
    float* Za = scratch + OFF_ZA;
    float* Zg = scratch + OFF_ZG;
    float* SH = scratch + OFF_SH;
    float* SE = scratch + OFF_SE;
    float* UH = scratch + OFF_UH;
    float* UE = scratch + OFF_UE;
    float* st_sum   = scratch + OFF_ST;
    float* st_sq    = st_sum + HID;
    float* bn_scale = st_sq + HID;
    float* bn_shift = bn_scale + HID;
    __half* WP   = (__half*)(scratch + OFF_WP);
    __half* Xa16 = (__half*)(scratch + OFF_XA16);
    __half* Xg16 = (__half*)(scratch + OFF_XG16);
    __half* e16  = (__half*)(scratch + OFF_E16);
    __half* h16  = (__half*)(scratch + OFF_H16);
    __half* u16  = (__half*)(scratch + OFF_U16);

    float* out_h = (float*)d_out;
    float* out_e = out_h + (size_t)N * D;
    float* out_u = out_e + (size_t)E * D;

    // Launch 1: zero accumulators (SH, SE, UH, UE, stats).
    {
        size_t nz = (size_t)MAXN * D * 2 + (size_t)MAXG * D * 2 + 2 * HID;
        zerok<<<2048, 256>>>(SH, nz);
    }
    // Launch 2: fused input converts.
    {
        int ne4 = E * D / 4, nh4 = N * D / 4, nu4 = G * D / 4;
        cvt_all<<<(ne4 + nh4 + nu4 + 255) / 256, 256>>>(e, h, u, e16, h16, u16, ne4, nh4, nu4);
    }
    // Launch 3: fused weight prep.
    prep_all<<<(3 * T1 + 3 * T3 + 2 * T2 + 255) / 256, 256>>>(bW1, bW2, aW1, aW2, gW1, gW2, WP);

    // ---- Bond path ----
    // Launch 4: Ph16 = fp16(h16 @ bW1a)
    run_gemm_mma(5, h16, WP + WPO_BW1A, nullptr, Ph16, N, 128, HID,
                 nullptr, nullptr, nullptr, nullptr, nullptr, nullptr, nullptr, nullptr, nullptr,
                 nullptr, nullptr, nullptr, nullptr);
    // Launch 5: U1
    run_gemm_mma(0, u16, WP + WPO_BW1C, bb1, U1, G, 128, HID,
                 nullptr, nullptr, nullptr, nullptr, nullptr, nullptr, nullptr, nullptr, nullptr,
                 nullptr, nullptr, nullptr, nullptr);
    // Launch 6 (ncu -s 5 captures this): the big fused e-GEMM.
    run_gemm_mma(1, e16, WP + WPO_BW1B, nullptr, Zb, E, 128, HID,
                 nullptr, nullptr, nullptr, nullptr, Ph16, U1, src, dst, gid, st_sum, st_sq,
                 h, SH);
    bn_prep<<<1, HID>>>(st_sum, st_sq, bg1, bbt, bn_scale, bn_shift, 1.f / (float)E);
    run_gemm_mma(2, Zb, WP + WPO_BW2, bb2, out_e, E, HID, D,
                 bn_scale, bn_shift, dst, SE, nullptr, nullptr, nullptr, nullptr, nullptr,
                 nullptr, nullptr, nullptr, nullptr);

    // ---- Atom path ----
    node_build<<<(N * 32 + 255) / 256, 256>>>(h, u, gid, SH, SE, Xa16, UE, N);
    run_gemm_mma(3, Xa16, WP + WPO_AW1, ab1, Za, N, HID, HID,
                 nullptr, nullptr, nullptr, nullptr, nullptr, nullptr, nullptr, nullptr, nullptr,
                 st_sum, st_sq, nullptr, nullptr);
    bn_prep<<<1, HID>>>(st_sum, st_sq, ag1, abt, bn_scale, bn_shift, 1.f / (float)N);
    run_gemm_mma(2, Za, WP + WPO_AW2, ab2, out_h, N, HID, D,
                 bn_scale, bn_shift, gid, UH, nullptr, nullptr, nullptr, nullptr, nullptr,
                 nullptr, nullptr, nullptr, nullptr);

    // ---- Global path ----
    graph_build<<<(G * 32 + 255) / 256, 256>>>(u, UH, UE, Xg16, G);
    run_gemm_mma(3, Xg16, WP + WPO_GW1, gb1, Zg, G, HID, HID,
                 nullptr, nullptr, nullptr, nullptr, nullptr, nullptr, nullptr, nullptr, nullptr,
                 st_sum, st_sq, nullptr, nullptr);
    bn_prep<<<1, HID>>>(st_sum, st_sq, gg1, gbt, bn_scale, bn_shift, 1.f / (float)G);
    run_gemm_mma(4, Zg, WP + WPO_GW2, gb2, out_u, G, HID, D,
                 bn_scale, bn_shift, nullptr, nullptr, nullptr, nullptr, nullptr, nullptr, nullptr,
                 nullptr, nullptr, nullptr, nullptr);
}